// round 13
// baseline (speedup 1.0000x reference)
#include <cuda_runtime.h>
#include <cuda_bf16.h>
#include <math.h>
#include <stdint.h>

#define D_DIM 1024
#define H_DIM 4096
#define NE 8
#define T_MAX 8192

#define BM 128
#define BN 128
#define BK 32
#define PAD 40   // bf16 elems per smem row (32 data + 8 pad) -> 80B stride, conflict-free ldmatrix

// ---------------- scratch (device globals; no allocation allowed) ----------------
__device__ int g_cnt[NE];
__device__ int g_base[NE];
__device__ int g_list[NE * T_MAX];     // packed entries: token*2 + slot
__device__ int g_top[2 * T_MAX];
__device__ float g_wt[2 * T_MAX];

__device__ __align__(16) __nv_bfloat16 g_xh[(size_t)T_MAX * D_DIM];
__device__ __align__(16) __nv_bfloat16 g_xl[(size_t)T_MAX * D_DIM];
__device__ __align__(16) __nv_bfloat16 g_w1h[(size_t)NE * H_DIM * D_DIM];
__device__ __align__(16) __nv_bfloat16 g_w1l[(size_t)NE * H_DIM * D_DIM];
__device__ __align__(16) __nv_bfloat16 g_w2h[(size_t)NE * D_DIM * H_DIM];
__device__ __align__(16) __nv_bfloat16 g_w2l[(size_t)NE * D_DIM * H_DIM];
__device__ __align__(16) __nv_bfloat16 g_hh[(size_t)2 * T_MAX * H_DIM];
__device__ __align__(16) __nv_bfloat16 g_hl[(size_t)2 * T_MAX * H_DIM];
__device__ __align__(16) float g_y[(size_t)2 * T_MAX * D_DIM];

// ---------------- helpers ----------------
__device__ __forceinline__ float gelu_f(float v) {
    return 0.5f * v * (1.0f + tanhf(0.7978845608028654f * (v + 0.044715f * v * v * v)));
}

#define LDSM4(R, addr) asm volatile( \
    "ldmatrix.sync.aligned.m8n8.x4.shared.b16 {%0,%1,%2,%3}, [%4];" \
    : "=r"(R[0]), "=r"(R[1]), "=r"(R[2]), "=r"(R[3]) : "r"(addr))

#define MMA_BF16(C, A, b0, b1) asm volatile( \
    "mma.sync.aligned.m16n8k16.row.col.f32.bf16.bf16.f32 " \
    "{%0,%1,%2,%3}, {%4,%5,%6,%7}, {%8,%9}, {%0,%1,%2,%3};" \
    : "+f"(C[0]), "+f"(C[1]), "+f"(C[2]), "+f"(C[3]) \
    : "r"(A[0]), "r"(A[1]), "r"(A[2]), "r"(A[3]), "r"(b0), "r"(b1))

// ---------------- router: one warp per token ----------------
__global__ void router_kernel(const float* __restrict__ x, const float* __restrict__ se,
                              const float* __restrict__ rw, const float* __restrict__ rb,
                              const int* __restrict__ sidx, int T) {
    if (blockIdx.x == 0 && threadIdx.x < NE) g_cnt[threadIdx.x] = 0;
    int w = (blockIdx.x * blockDim.x + threadIdx.x) >> 5;
    int lane = threadIdx.x & 31;
    if (w >= T) return;
    int si = sidx[0];
    if (si < 0 || si > 9) {                 // dtype-robust: maybe float bits
        float f = __int_as_float(si);
        si = (int)f;
        if (si < 0 || si > 9) si = 0;
    }
    const float* xr = x + (size_t)w * D_DIM;
    const float* sb = se + (size_t)si * D_DIM;
    float acc[NE];
#pragma unroll
    for (int e = 0; e < NE; e++) acc[e] = 0.f;
    for (int d = lane; d < D_DIM; d += 32) {
        float xv = xr[d] + sb[d];
#pragma unroll
        for (int e = 0; e < NE; e++) acc[e] += xv * rw[e * D_DIM + d];
    }
#pragma unroll
    for (int e = 0; e < NE; e++) {
#pragma unroll
        for (int o = 16; o > 0; o >>= 1) acc[e] += __shfl_xor_sync(0xffffffffu, acc[e], o);
    }
    if (lane == 0) {
        float v0 = -1e30f; int i0 = 0;
#pragma unroll
        for (int e = 0; e < NE; e++) { float v = acc[e] + rb[e]; if (v > v0) { v0 = v; i0 = e; } }
        float v1 = -1e30f; int i1 = 0;
#pragma unroll
        for (int e = 0; e < NE; e++) { float v = acc[e] + rb[e]; if (e != i0 && v > v1) { v1 = v; i1 = e; } }
        float ew = expf(v1 - v0);
        float inv = 1.f / (1.f + ew);
        g_top[w * 2] = i0; g_top[w * 2 + 1] = i1;
        g_wt[w * 2] = inv; g_wt[w * 2 + 1] = ew * inv;
    }
}

// ---------------- bucket tokens per expert ----------------
__global__ void bucket_kernel(int T) {
    int t = blockIdx.x * blockDim.x + threadIdx.x;
    if (t >= T) return;
#pragma unroll
    for (int s = 0; s < 2; s++) {
        int e = g_top[t * 2 + s];
        int pos = atomicAdd(&g_cnt[e], 1);
        g_list[e * T_MAX + pos] = t * 2 + s;
    }
}

__global__ void scan_kernel() {
    if (threadIdx.x == 0) {
        int s = 0;
#pragma unroll
        for (int e = 0; e < NE; e++) { g_base[e] = s; s += g_cnt[e]; }
    }
}

// ---------------- fp32 -> bf16 hi/lo split planes ----------------
template <int W>
__global__ void split_kernel(const float* __restrict__ src, size_t n) {
    __nv_bfloat16* hi; __nv_bfloat16* lo;
    if (W == 0)      { hi = g_xh;  lo = g_xl;  }
    else if (W == 1) { hi = g_w1h; lo = g_w1l; }
    else             { hi = g_w2h; lo = g_w2l; }
    size_t stride = (size_t)gridDim.x * blockDim.x;
    for (size_t i = (size_t)blockIdx.x * blockDim.x + threadIdx.x; i < n; i += stride) {
        float v = src[i];
        __nv_bfloat16 h = __float2bfloat16(v);
        hi[i] = h;
        lo[i] = __float2bfloat16(v - __bfloat162float(h));
    }
}

// ---------------- grouped GEMM (split-bf16, 3 mma per tile-pair) ----------------
// FIRST: h = gelu(x[tok] @ fc1_w[e]^T + b1)  -> bf16 hi/lo planes
// !FIRST: y[id2] = h_row @ fc2_w[e]^T + b2   -> fp32
template <bool FIRST>
__global__ __launch_bounds__(256, 2) void moe_gemm(const float* __restrict__ bias, int T) {
    constexpr int KT = FIRST ? D_DIM : H_DIM;
    constexpr int NT = FIRST ? H_DIM : D_DIM;
    const int e = blockIdx.z;
    const int cnt = g_cnt[e];
    const int m0 = blockIdx.y * BM;
    if (m0 >= cnt) return;
    const int n0 = blockIdx.x * BN;
    const int base = g_base[e];

    const __nv_bfloat16* __restrict__ Ahg = FIRST ? g_xh : g_hh;
    const __nv_bfloat16* __restrict__ Alg = FIRST ? g_xl : g_hl;
    const __nv_bfloat16* __restrict__ Bhg = FIRST ? g_w1h : g_w2h;
    const __nv_bfloat16* __restrict__ Blg = FIRST ? g_w1l : g_w2l;
    const size_t bOff = (size_t)e * NT * KT;

    __shared__ __align__(16) __nv_bfloat16 sAh[BM * PAD];
    __shared__ __align__(16) __nv_bfloat16 sAl[BM * PAD];
    __shared__ __align__(16) __nv_bfloat16 sBh[BN * PAD];
    __shared__ __align__(16) __nv_bfloat16 sBl[BN * PAD];
    __shared__ int sRow[BM];
    __shared__ int sId2[BM];

    const int tid = threadIdx.x;
    for (int i = tid; i < BM; i += 256) {
        int p = m0 + i;
        int pc = p < cnt ? p : cnt - 1;   // clamp: duplicate row, output masked later
        int id2 = g_list[e * T_MAX + pc];
        sId2[i] = id2;
        sRow[i] = FIRST ? (id2 >> 1) : (base + pc);
    }

    const int wid = tid >> 5, lane = tid & 31;
    const int wm = (wid & 3) * 32;   // warp row offset (4 warps over M)
    const int wn = (wid >> 2) * 64;  // warp col offset (2 warps over N)
    const int f = lane >> 3, r8 = lane & 7;
    const int aRow = (f & 1) * 8 + r8, aCol = (f >> 1) * 8;  // ldmatrix x4: a0..a3 frag order
    const int bRow = (f >> 1) * 8 + r8, bCol = (f & 1) * 8;  // frags: k-lo, k-hi, next-n8 pair

    float acc[2][8][4];
#pragma unroll
    for (int a = 0; a < 2; a++)
#pragma unroll
        for (int b = 0; b < 8; b++)
#pragma unroll
            for (int c = 0; c < 4; c++) acc[a][b][c] = 0.f;

#pragma unroll 1
    for (int k0 = 0; k0 < KT; k0 += BK) {
        __syncthreads();
#pragma unroll
        for (int it = 0; it < 2; ++it) {
            int i = tid + it * 256;
            int row = i >> 2, part = i & 3;
            size_t ga = (size_t)sRow[row] * KT + (k0 + part * 8);
            uint4 vh = *(const uint4*)(Ahg + ga);
            uint4 vl = *(const uint4*)(Alg + ga);
            size_t gb = bOff + (size_t)(n0 + row) * KT + (k0 + part * 8);
            uint4 wh = *(const uint4*)(Bhg + gb);
            uint4 wl = *(const uint4*)(Blg + gb);
            *(uint4*)(sAh + row * PAD + part * 8) = vh;
            *(uint4*)(sAl + row * PAD + part * 8) = vl;
            *(uint4*)(sBh + row * PAD + part * 8) = wh;
            *(uint4*)(sBl + row * PAD + part * 8) = wl;
        }
        __syncthreads();
#pragma unroll
        for (int kk = 0; kk < BK; kk += 16) {
            uint32_t ah[2][4], al[2][4];
#pragma unroll
            for (int mt = 0; mt < 2; ++mt) {
                uint32_t adh = (uint32_t)__cvta_generic_to_shared(sAh + (wm + mt * 16 + aRow) * PAD + kk + aCol);
                LDSM4(ah[mt], adh);
                uint32_t adl = (uint32_t)__cvta_generic_to_shared(sAl + (wm + mt * 16 + aRow) * PAD + kk + aCol);
                LDSM4(al[mt], adl);
            }
#pragma unroll
            for (int np = 0; np < 4; ++np) {
                uint32_t bh[4], bl[4];
                uint32_t bdh = (uint32_t)__cvta_generic_to_shared(sBh + (wn + np * 16 + bRow) * PAD + kk + bCol);
                LDSM4(bh, bdh);
                uint32_t bdl = (uint32_t)__cvta_generic_to_shared(sBl + (wn + np * 16 + bRow) * PAD + kk + bCol);
                LDSM4(bl, bdl);
#pragma unroll
                for (int mt = 0; mt < 2; ++mt) {
                    // split product: Ah*Bh + Ah*Bl + Al*Bh (Al*Bl ~1.5e-5, dropped)
                    MMA_BF16(acc[mt][np * 2],     ah[mt], bh[0], bh[1]);
                    MMA_BF16(acc[mt][np * 2],     ah[mt], bl[0], bl[1]);
                    MMA_BF16(acc[mt][np * 2],     al[mt], bh[0], bh[1]);
                    MMA_BF16(acc[mt][np * 2 + 1], ah[mt], bh[2], bh[3]);
                    MMA_BF16(acc[mt][np * 2 + 1], ah[mt], bl[2], bl[3]);
                    MMA_BF16(acc[mt][np * 2 + 1], al[mt], bh[2], bh[3]);
                }
            }
        }
    }

    // epilogue
    const int g = lane >> 2, tg = lane & 3;
#pragma unroll
    for (int mt = 0; mt < 2; ++mt) {
#pragma unroll
        for (int nt = 0; nt < 8; ++nt) {
            int cc = n0 + wn + nt * 8 + tg * 2;
            float bv0 = bias[(size_t)e * NT + cc];
            float bv1 = bias[(size_t)e * NT + cc + 1];
#pragma unroll
            for (int hh = 0; hh < 2; ++hh) {
                int row = wm + mt * 16 + g + hh * 8;
                int p = m0 + row;
                if (p < cnt) {
                    float v0 = acc[mt][nt][hh * 2 + 0] + bv0;
                    float v1 = acc[mt][nt][hh * 2 + 1] + bv1;
                    if (FIRST) {
                        v0 = gelu_f(v0); v1 = gelu_f(v1);
                        size_t o = (size_t)(base + p) * H_DIM + cc;
                        __nv_bfloat16 h0 = __float2bfloat16(v0), h1 = __float2bfloat16(v1);
                        __nv_bfloat162 hv; hv.x = h0; hv.y = h1;
                        *(__nv_bfloat162*)(g_hh + o) = hv;
                        __nv_bfloat162 lv;
                        lv.x = __float2bfloat16(v0 - __bfloat162float(h0));
                        lv.y = __float2bfloat16(v1 - __bfloat162float(h1));
                        *(__nv_bfloat162*)(g_hl + o) = lv;
                    } else {
                        int id2 = sId2[row];
                        size_t o = (size_t)id2 * D_DIM + cc;
                        float2 vv; vv.x = v0; vv.y = v1;
                        *(float2*)(g_y + o) = vv;
                    }
                }
            }
        }
    }
}

// ---------------- weighted combine of the two expert rows per token ----------------
// NOTE R12 bug fix: element count is derived from T inside the kernel (was
// previously passed as T instead of T*D_DIM, masking 1023/1024 of the output).
__global__ void combine_kernel(float* __restrict__ out, int T) {
    int total = T * D_DIM;
    int i = blockIdx.x * blockDim.x + threadIdx.x;
    if (i >= total) return;
    int t = i >> 10;            // / D_DIM
    int d = i & (D_DIM - 1);
    float w0 = g_wt[t * 2], w1 = g_wt[t * 2 + 1];
    out[i] = w0 * g_y[(size_t)(t * 2) * D_DIM + d] + w1 * g_y[(size_t)(t * 2 + 1) * D_DIM + d];
}

// ---------------- launch: size-based input binding (permutation-robust) ----------------
extern "C" void kernel_launch(void* const* d_in, const int* in_sizes, int n_in,
                              void* d_out, int out_size) {
    const float *x = nullptr, *se = nullptr, *rw = nullptr, *rb = nullptr;
    const float *w1 = nullptr, *b1 = nullptr, *w2 = nullptr, *b2 = nullptr;
    const int *sidx = nullptr;
    long long sz_x = 0;
    int i8192[2]; int n8192 = 0; int irb = -1;

    for (int i = 0; i < n_in; i++) {
        long long s = in_sizes[i];
        const float* p = (const float*)d_in[i];
        if (s == 8388608LL)        { x = p; sz_x = s; }                 // (4,2048,1024)
        else if (s == 10240LL)     { se = p; }                          // (10,1024)
        else if (s == 8LL)         { rb = p; irb = i; }                 // (8,)
        else if (s == 32768LL)     { b1 = p; }                          // (8,4096)
        else if (s == 1LL)         { sidx = (const int*)d_in[i]; }      // scalar
        else if (s == 33554432LL)  { if (!w1) w1 = p; else w2 = p; }    // fc1_w then fc2_w
        else if (s == 8192LL)      { if (n8192 < 2) i8192[n8192++] = i; } // router_w / fc2_b
    }
    // Disambiguate the two 8192-element inputs: router_w is adjacent to router_b
    // in signature/dict order (rw@2, rb@3) and alphabetical order (rb@4, rw@5).
    if (n8192 == 2) {
        int a = i8192[0], b = i8192[1];
        int da = a > irb ? a - irb : irb - a;
        int db = b > irb ? b - irb : irb - b;
        if (da <= db) { rw = (const float*)d_in[a]; b2 = (const float*)d_in[b]; }
        else          { rw = (const float*)d_in[b]; b2 = (const float*)d_in[a]; }
    } else if (n8192 == 1) {
        rw = (const float*)d_in[i8192[0]]; b2 = rw; // degenerate fallback
    }

    int T = (int)(sz_x / D_DIM);   // 8192

    router_kernel<<<(T * 32 + 255) / 256, 256>>>(x, se, rw, rb, sidx, T);
    bucket_kernel<<<(T + 255) / 256, 256>>>(T);
    scan_kernel<<<1, 32>>>();

    size_t nx = (size_t)T * D_DIM;
    size_t nw = (size_t)NE * H_DIM * D_DIM;
    split_kernel<0><<<4096, 256>>>(x, nx);
    split_kernel<1><<<16384, 256>>>(w1, nw);
    split_kernel<2><<<16384, 256>>>(w2, nw);

    dim3 grid1(H_DIM / BN, (T + BM - 1) / BM, NE);
    moe_gemm<true><<<grid1, 256>>>(b1, T);
    dim3 grid2(D_DIM / BN, (T + BM - 1) / BM, NE);
    moe_gemm<false><<<grid2, 256>>>(b2, T);

    combine_kernel<<<(T * D_DIM + 255) / 256, 256>>>((float*)d_out, T);
}

// round 14
// speedup vs baseline: 1.0039x; 1.0039x over previous
#include <cuda_runtime.h>
#include <cuda_bf16.h>
#include <math.h>
#include <stdint.h>

#define D_DIM 1024
#define H_DIM 4096
#define NE 8
#define T_MAX 8192

#define BM 128
#define BN 128
#define BK 32
#define PAD 40   // bf16 elems per smem row (32 data + 8 pad) -> 80B stride, conflict-free ldmatrix

// ---------------- scratch (device globals; no allocation allowed) ----------------
__device__ int g_cnt[NE];
__device__ int g_base[NE];
__device__ int g_list[NE * T_MAX];     // packed entries: token*2 + slot
__device__ int g_top[2 * T_MAX];
__device__ float g_wt[2 * T_MAX];

__device__ __align__(16) __nv_bfloat16 g_xh[(size_t)T_MAX * D_DIM];
__device__ __align__(16) __nv_bfloat16 g_xl[(size_t)T_MAX * D_DIM];
__device__ __align__(16) __nv_bfloat16 g_w1h[(size_t)NE * H_DIM * D_DIM];
__device__ __align__(16) __nv_bfloat16 g_w1l[(size_t)NE * H_DIM * D_DIM];
__device__ __align__(16) __nv_bfloat16 g_w2h[(size_t)NE * D_DIM * H_DIM];
__device__ __align__(16) __nv_bfloat16 g_w2l[(size_t)NE * D_DIM * H_DIM];
__device__ __align__(16) __nv_bfloat16 g_hh[(size_t)2 * T_MAX * H_DIM];
__device__ __align__(16) __nv_bfloat16 g_hl[(size_t)2 * T_MAX * H_DIM];
__device__ __align__(16) float g_y[(size_t)2 * T_MAX * D_DIM];

// ---------------- helpers ----------------
__device__ __forceinline__ float gelu_f(float v) {
    return 0.5f * v * (1.0f + tanhf(0.7978845608028654f * (v + 0.044715f * v * v * v)));
}

#define LDSM4(R, addr) asm volatile( \
    "ldmatrix.sync.aligned.m8n8.x4.shared.b16 {%0,%1,%2,%3}, [%4];" \
    : "=r"(R[0]), "=r"(R[1]), "=r"(R[2]), "=r"(R[3]) : "r"(addr))

#define MMA_BF16(C, A, b0, b1) asm volatile( \
    "mma.sync.aligned.m16n8k16.row.col.f32.bf16.bf16.f32 " \
    "{%0,%1,%2,%3}, {%4,%5,%6,%7}, {%8,%9}, {%0,%1,%2,%3};" \
    : "+f"(C[0]), "+f"(C[1]), "+f"(C[2]), "+f"(C[3]) \
    : "r"(A[0]), "r"(A[1]), "r"(A[2]), "r"(A[3]), "r"(b0), "r"(b1))

// ---------------- router: one warp per token ----------------
__global__ void router_kernel(const float* __restrict__ x, const float* __restrict__ se,
                              const float* __restrict__ rw, const float* __restrict__ rb,
                              const int* __restrict__ sidx, int T) {
    if (blockIdx.x == 0 && threadIdx.x < NE) g_cnt[threadIdx.x] = 0;
    int w = (blockIdx.x * blockDim.x + threadIdx.x) >> 5;
    int lane = threadIdx.x & 31;
    if (w >= T) return;
    int si = sidx[0];
    if (si < 0 || si > 9) {                 // dtype-robust: maybe float bits
        float f = __int_as_float(si);
        si = (int)f;
        if (si < 0 || si > 9) si = 0;
    }
    const float* xr = x + (size_t)w * D_DIM;
    const float* sb = se + (size_t)si * D_DIM;
    float acc[NE];
#pragma unroll
    for (int e = 0; e < NE; e++) acc[e] = 0.f;
    for (int d = lane; d < D_DIM; d += 32) {
        float xv = xr[d] + sb[d];
#pragma unroll
        for (int e = 0; e < NE; e++) acc[e] += xv * rw[e * D_DIM + d];
    }
#pragma unroll
    for (int e = 0; e < NE; e++) {
#pragma unroll
        for (int o = 16; o > 0; o >>= 1) acc[e] += __shfl_xor_sync(0xffffffffu, acc[e], o);
    }
    if (lane == 0) {
        float v0 = -1e30f; int i0 = 0;
#pragma unroll
        for (int e = 0; e < NE; e++) { float v = acc[e] + rb[e]; if (v > v0) { v0 = v; i0 = e; } }
        float v1 = -1e30f; int i1 = 0;
#pragma unroll
        for (int e = 0; e < NE; e++) { float v = acc[e] + rb[e]; if (e != i0 && v > v1) { v1 = v; i1 = e; } }
        float ew = expf(v1 - v0);
        float inv = 1.f / (1.f + ew);
        g_top[w * 2] = i0; g_top[w * 2 + 1] = i1;
        g_wt[w * 2] = inv; g_wt[w * 2 + 1] = ew * inv;
    }
}

// ---------------- bucket tokens per expert ----------------
__global__ void bucket_kernel(int T) {
    int t = blockIdx.x * blockDim.x + threadIdx.x;
    if (t >= T) return;
#pragma unroll
    for (int s = 0; s < 2; s++) {
        int e = g_top[t * 2 + s];
        int pos = atomicAdd(&g_cnt[e], 1);
        g_list[e * T_MAX + pos] = t * 2 + s;
    }
}

__global__ void scan_kernel() {
    if (threadIdx.x == 0) {
        int s = 0;
#pragma unroll
        for (int e = 0; e < NE; e++) { g_base[e] = s; s += g_cnt[e]; }
    }
}

// ---------------- fp32 -> bf16 hi/lo split planes ----------------
template <int W>
__global__ void split_kernel(const float* __restrict__ src, size_t n) {
    __nv_bfloat16* hi; __nv_bfloat16* lo;
    if (W == 0)      { hi = g_xh;  lo = g_xl;  }
    else if (W == 1) { hi = g_w1h; lo = g_w1l; }
    else             { hi = g_w2h; lo = g_w2l; }
    size_t stride = (size_t)gridDim.x * blockDim.x;
    for (size_t i = (size_t)blockIdx.x * blockDim.x + threadIdx.x; i < n; i += stride) {
        float v = src[i];
        __nv_bfloat16 h = __float2bfloat16(v);
        hi[i] = h;
        lo[i] = __float2bfloat16(v - __bfloat162float(h));
    }
}

// ---------------- grouped GEMM (split-bf16, 3 mma per tile-pair) ----------------
// FIRST: h = gelu(x[tok] @ fc1_w[e]^T + b1)  -> bf16 hi/lo planes
// !FIRST: y[id2] = h_row @ fc2_w[e]^T + b2   -> fp32
template <bool FIRST>
__global__ __launch_bounds__(256, 2) void moe_gemm(const float* __restrict__ bias, int T) {
    constexpr int KT = FIRST ? D_DIM : H_DIM;
    constexpr int NT = FIRST ? H_DIM : D_DIM;
    const int e = blockIdx.z;
    const int cnt = g_cnt[e];
    const int m0 = blockIdx.y * BM;
    if (m0 >= cnt) return;
    const int n0 = blockIdx.x * BN;
    const int base = g_base[e];

    const __nv_bfloat16* __restrict__ Ahg = FIRST ? g_xh : g_hh;
    const __nv_bfloat16* __restrict__ Alg = FIRST ? g_xl : g_hl;
    const __nv_bfloat16* __restrict__ Bhg = FIRST ? g_w1h : g_w2h;
    const __nv_bfloat16* __restrict__ Blg = FIRST ? g_w1l : g_w2l;
    const size_t bOff = (size_t)e * NT * KT;

    __shared__ __align__(16) __nv_bfloat16 sAh[BM * PAD];
    __shared__ __align__(16) __nv_bfloat16 sAl[BM * PAD];
    __shared__ __align__(16) __nv_bfloat16 sBh[BN * PAD];
    __shared__ __align__(16) __nv_bfloat16 sBl[BN * PAD];
    __shared__ int sRow[BM];
    __shared__ int sId2[BM];

    const int tid = threadIdx.x;
    for (int i = tid; i < BM; i += 256) {
        int p = m0 + i;
        int pc = p < cnt ? p : cnt - 1;   // clamp: duplicate row, output masked later
        int id2 = g_list[e * T_MAX + pc];
        sId2[i] = id2;
        sRow[i] = FIRST ? (id2 >> 1) : (base + pc);
    }

    const int wid = tid >> 5, lane = tid & 31;
    const int wm = (wid & 3) * 32;   // warp row offset (4 warps over M)
    const int wn = (wid >> 2) * 64;  // warp col offset (2 warps over N)
    const int f = lane >> 3, r8 = lane & 7;
    const int aRow = (f & 1) * 8 + r8, aCol = (f >> 1) * 8;  // ldmatrix x4: a0..a3 frag order
    const int bRow = (f >> 1) * 8 + r8, bCol = (f & 1) * 8;  // frags: k-lo, k-hi, next-n8 pair

    float acc[2][8][4];
#pragma unroll
    for (int a = 0; a < 2; a++)
#pragma unroll
        for (int b = 0; b < 8; b++)
#pragma unroll
            for (int c = 0; c < 4; c++) acc[a][b][c] = 0.f;

#pragma unroll 1
    for (int k0 = 0; k0 < KT; k0 += BK) {
        __syncthreads();
#pragma unroll
        for (int it = 0; it < 2; ++it) {
            int i = tid + it * 256;
            int row = i >> 2, part = i & 3;
            size_t ga = (size_t)sRow[row] * KT + (k0 + part * 8);
            uint4 vh = *(const uint4*)(Ahg + ga);
            uint4 vl = *(const uint4*)(Alg + ga);
            size_t gb = bOff + (size_t)(n0 + row) * KT + (k0 + part * 8);
            uint4 wh = *(const uint4*)(Bhg + gb);
            uint4 wl = *(const uint4*)(Blg + gb);
            *(uint4*)(sAh + row * PAD + part * 8) = vh;
            *(uint4*)(sAl + row * PAD + part * 8) = vl;
            *(uint4*)(sBh + row * PAD + part * 8) = wh;
            *(uint4*)(sBl + row * PAD + part * 8) = wl;
        }
        __syncthreads();
#pragma unroll
        for (int kk = 0; kk < BK; kk += 16) {
            uint32_t ah[2][4], al[2][4];
#pragma unroll
            for (int mt = 0; mt < 2; ++mt) {
                uint32_t adh = (uint32_t)__cvta_generic_to_shared(sAh + (wm + mt * 16 + aRow) * PAD + kk + aCol);
                LDSM4(ah[mt], adh);
                uint32_t adl = (uint32_t)__cvta_generic_to_shared(sAl + (wm + mt * 16 + aRow) * PAD + kk + aCol);
                LDSM4(al[mt], adl);
            }
#pragma unroll
            for (int np = 0; np < 4; ++np) {
                uint32_t bh[4], bl[4];
                uint32_t bdh = (uint32_t)__cvta_generic_to_shared(sBh + (wn + np * 16 + bRow) * PAD + kk + bCol);
                LDSM4(bh, bdh);
                uint32_t bdl = (uint32_t)__cvta_generic_to_shared(sBl + (wn + np * 16 + bRow) * PAD + kk + bCol);
                LDSM4(bl, bdl);
#pragma unroll
                for (int mt = 0; mt < 2; ++mt) {
                    // split product: Ah*Bh + Ah*Bl + Al*Bh (Al*Bl ~1.5e-5, dropped)
                    MMA_BF16(acc[mt][np * 2],     ah[mt], bh[0], bh[1]);
                    MMA_BF16(acc[mt][np * 2],     ah[mt], bl[0], bl[1]);
                    MMA_BF16(acc[mt][np * 2],     al[mt], bh[0], bh[1]);
                    MMA_BF16(acc[mt][np * 2 + 1], ah[mt], bh[2], bh[3]);
                    MMA_BF16(acc[mt][np * 2 + 1], ah[mt], bl[2], bl[3]);
                    MMA_BF16(acc[mt][np * 2 + 1], al[mt], bh[2], bh[3]);
                }
            }
        }
    }

    // epilogue
    const int g = lane >> 2, tg = lane & 3;
#pragma unroll
    for (int mt = 0; mt < 2; ++mt) {
#pragma unroll
        for (int nt = 0; nt < 8; ++nt) {
            int cc = n0 + wn + nt * 8 + tg * 2;
            float bv0 = bias[(size_t)e * NT + cc];
            float bv1 = bias[(size_t)e * NT + cc + 1];
#pragma unroll
            for (int hh = 0; hh < 2; ++hh) {
                int row = wm + mt * 16 + g + hh * 8;
                int p = m0 + row;
                if (p < cnt) {
                    float v0 = acc[mt][nt][hh * 2 + 0] + bv0;
                    float v1 = acc[mt][nt][hh * 2 + 1] + bv1;
                    if (FIRST) {
                        v0 = gelu_f(v0); v1 = gelu_f(v1);
                        size_t o = (size_t)(base + p) * H_DIM + cc;
                        __nv_bfloat16 h0 = __float2bfloat16(v0), h1 = __float2bfloat16(v1);
                        __nv_bfloat162 hv; hv.x = h0; hv.y = h1;
                        *(__nv_bfloat162*)(g_hh + o) = hv;
                        __nv_bfloat162 lv;
                        lv.x = __float2bfloat16(v0 - __bfloat162float(h0));
                        lv.y = __float2bfloat16(v1 - __bfloat162float(h1));
                        *(__nv_bfloat162*)(g_hl + o) = lv;
                    } else {
                        int id2 = sId2[row];
                        size_t o = (size_t)id2 * D_DIM + cc;
                        float2 vv; vv.x = v0; vv.y = v1;
                        *(float2*)(g_y + o) = vv;
                    }
                }
            }
        }
    }
}

// ---------------- weighted combine of the two expert rows per token ----------------
// NOTE R12 bug fix: element count is derived from T inside the kernel (was
// previously passed as T instead of T*D_DIM, masking 1023/1024 of the output).
__global__ void combine_kernel(float* __restrict__ out, int T) {
    int total = T * D_DIM;
    int i = blockIdx.x * blockDim.x + threadIdx.x;
    if (i >= total) return;
    int t = i >> 10;            // / D_DIM
    int d = i & (D_DIM - 1);
    float w0 = g_wt[t * 2], w1 = g_wt[t * 2 + 1];
    out[i] = w0 * g_y[(size_t)(t * 2) * D_DIM + d] + w1 * g_y[(size_t)(t * 2 + 1) * D_DIM + d];
}

// ---------------- launch: size-based input binding (permutation-robust) ----------------
extern "C" void kernel_launch(void* const* d_in, const int* in_sizes, int n_in,
                              void* d_out, int out_size) {
    const float *x = nullptr, *se = nullptr, *rw = nullptr, *rb = nullptr;
    const float *w1 = nullptr, *b1 = nullptr, *w2 = nullptr, *b2 = nullptr;
    const int *sidx = nullptr;
    long long sz_x = 0;
    int i8192[2]; int n8192 = 0; int irb = -1;

    for (int i = 0; i < n_in; i++) {
        long long s = in_sizes[i];
        const float* p = (const float*)d_in[i];
        if (s == 8388608LL)        { x = p; sz_x = s; }                 // (4,2048,1024)
        else if (s == 10240LL)     { se = p; }                          // (10,1024)
        else if (s == 8LL)         { rb = p; irb = i; }                 // (8,)
        else if (s == 32768LL)     { b1 = p; }                          // (8,4096)
        else if (s == 1LL)         { sidx = (const int*)d_in[i]; }      // scalar
        else if (s == 33554432LL)  { if (!w1) w1 = p; else w2 = p; }    // fc1_w then fc2_w
        else if (s == 8192LL)      { if (n8192 < 2) i8192[n8192++] = i; } // router_w / fc2_b
    }
    // Disambiguate the two 8192-element inputs: router_w is adjacent to router_b
    // in signature/dict order (rw@2, rb@3) and alphabetical order (rb@4, rw@5).
    if (n8192 == 2) {
        int a = i8192[0], b = i8192[1];
        int da = a > irb ? a - irb : irb - a;
        int db = b > irb ? b - irb : irb - b;
        if (da <= db) { rw = (const float*)d_in[a]; b2 = (const float*)d_in[b]; }
        else          { rw = (const float*)d_in[b]; b2 = (const float*)d_in[a]; }
    } else if (n8192 == 1) {
        rw = (const float*)d_in[i8192[0]]; b2 = rw; // degenerate fallback
    }

    int T = (int)(sz_x / D_DIM);   // 8192

    router_kernel<<<(T * 32 + 255) / 256, 256>>>(x, se, rw, rb, sidx, T);
    bucket_kernel<<<(T + 255) / 256, 256>>>(T);
    scan_kernel<<<1, 32>>>();

    size_t nx = (size_t)T * D_DIM;
    size_t nw = (size_t)NE * H_DIM * D_DIM;
    split_kernel<0><<<4096, 256>>>(x, nx);
    split_kernel<1><<<16384, 256>>>(w1, nw);
    split_kernel<2><<<16384, 256>>>(w2, nw);

    dim3 grid1(H_DIM / BN, (T + BM - 1) / BM, NE);
    moe_gemm<true><<<grid1, 256>>>(b1, T);
    dim3 grid2(D_DIM / BN, (T + BM - 1) / BM, NE);
    moe_gemm<false><<<grid2, 256>>>(b2, T);

    combine_kernel<<<(T * D_DIM + 255) / 256, 256>>>((float*)d_out, T);
}